// round 3
// baseline (speedup 1.0000x reference)
#include <cuda_runtime.h>
#include <cuda_fp16.h>
#include <mma.h>

using namespace nvcuda;

#define TOK 8192      // B*S
#define DD  1024      // model dim
#define FF  4096      // ffn dim
#define NE  8         // experts
// top-k = 2

// ---------------- device scratch (static globals; no allocation) ----------------
__device__ __half g_Xh  [(size_t)TOK * DD];          // 16 MB  rmsnorm'd x, fp16
__device__ __half g_W1ah[(size_t)NE * DD * FF];      // 64 MB
__device__ __half g_W1bh[(size_t)NE * DD * FF];      // 64 MB
__device__ __half g_W2h [(size_t)NE * FF * DD];      // 64 MB
__device__ __half g_H   [(size_t)2 * TOK * FF];      // 128 MB  silu(a)*b per assignment
__device__ float  g_Y   [(size_t)2 * TOK * DD];      // 64 MB   expert output per assignment
__device__ int    g_cnt [NE];
__device__ int    g_off [NE];
__device__ int    g_tlist[NE * TOK];                 // token ids per expert
__device__ int    g_loc [2 * TOK];                   // local slot of assignment k of token t
__device__ int    g_exp [2 * TOK];                   // expert of assignment
__device__ float  g_gw  [2 * TOK];                   // gate weight of assignment

// ---------------- small kernels ----------------
__global__ void k_init_cnt() {
    if (threadIdx.x < NE) g_cnt[threadIdx.x] = 0;
}

// fp32 -> fp16 weight conversion. which: 0=W1a, 1=W1b, 2=W2
__global__ void k_cvt(const float* __restrict__ src, int which) {
    __half* dst = (which == 0) ? g_W1ah : (which == 1) ? g_W1bh : g_W2h;
    size_t i = (size_t)blockIdx.x * blockDim.x + threadIdx.x;   // float4 index
    float4 v = ((const float4*)src)[i];
    __half2* d2 = (__half2*)dst;
    d2[2 * i]     = __floats2half2_rn(v.x, v.y);
    d2[2 * i + 1] = __floats2half2_rn(v.z, v.w);
}

// RMSNorm + gating + top-2 softmax + scatter. One block per token, 256 threads.
__global__ void k_rms_gate(const float* __restrict__ x,
                           const float* __restrict__ lnw,
                           const float* __restrict__ Wg,
                           const float* __restrict__ bg) {
    int t = blockIdx.x;
    int tid = threadIdx.x, warp = tid >> 5, lane = tid & 31;

    __shared__ float red[8];
    __shared__ float wlog[8][8];
    __shared__ float sscale;

    float4 v = ((const float4*)(x + (size_t)t * DD))[tid];
    float ss = v.x * v.x + v.y * v.y + v.z * v.z + v.w * v.w;
#pragma unroll
    for (int o = 16; o; o >>= 1) ss += __shfl_xor_sync(0xffffffffu, ss, o);
    if (lane == 0) red[warp] = ss;
    __syncthreads();
    if (tid == 0) {
        float tot = 0.f;
#pragma unroll
        for (int w = 0; w < 8; w++) tot += red[w];
        sscale = rsqrtf(tot * (1.0f / (float)DD) + 1.1920928955078125e-7f);
    }
    __syncthreads();
    float s = sscale;

    float4 lw = ((const float4*)lnw)[tid];
    float xn0 = v.x * s * lw.x;
    float xn1 = v.y * s * lw.y;
    float xn2 = v.z * s * lw.z;
    float xn3 = v.w * s * lw.w;

    __half2* xh = (__half2*)(g_Xh + (size_t)t * DD);
    xh[2 * tid]     = __floats2half2_rn(xn0, xn1);
    xh[2 * tid + 1] = __floats2half2_rn(xn2, xn3);

    // gating logits in fp32 (routing decisions must match reference)
    float p[8];
#pragma unroll
    for (int e = 0; e < 8; e++) p[e] = 0.f;
    int d = tid * 4;
#pragma unroll
    for (int j = 0; j < 4; j++) {
        float xv = (j == 0) ? xn0 : (j == 1) ? xn1 : (j == 2) ? xn2 : xn3;
        const float* wr = Wg + (size_t)(d + j) * NE;
#pragma unroll
        for (int e = 0; e < 8; e++) p[e] += xv * __ldg(&wr[e]);
    }
#pragma unroll
    for (int o = 16; o; o >>= 1) {
#pragma unroll
        for (int e = 0; e < 8; e++) p[e] += __shfl_xor_sync(0xffffffffu, p[e], o);
    }
    if (lane == 0) {
#pragma unroll
        for (int e = 0; e < 8; e++) wlog[warp][e] = p[e];
    }
    __syncthreads();

    if (tid == 0) {
        float lg[8];
#pragma unroll
        for (int e = 0; e < 8; e++) {
            float acc = bg[e];
#pragma unroll
            for (int w = 0; w < 8; w++) acc += wlog[w][e];
            lg[e] = acc;
        }
        // top-2 with lowest-index tiebreak (matches jax.lax.top_k)
        int i1 = 0;
#pragma unroll
        for (int e = 1; e < 8; e++) if (lg[e] > lg[i1]) i1 = e;
        int i2 = -1;
#pragma unroll
        for (int e = 0; e < 8; e++) {
            if (e == i1) continue;
            if (i2 < 0 || lg[e] > lg[i2]) i2 = e;
        }
        float z  = expf(lg[i2] - lg[i1]);   // <= 1
        float w1 = 1.0f / (1.0f + z);
        float w2 = 1.0f - w1;

        int p1 = atomicAdd(&g_cnt[i1], 1);
        g_tlist[i1 * TOK + p1] = t;
        g_loc[2 * t] = p1; g_exp[2 * t] = i1; g_gw[2 * t] = w1;

        int p2 = atomicAdd(&g_cnt[i2], 1);
        g_tlist[i2 * TOK + p2] = t;
        g_loc[2 * t + 1] = p2; g_exp[2 * t + 1] = i2; g_gw[2 * t + 1] = w2;
    }
}

__global__ void k_prefix() {
    int acc = 0;
#pragma unroll
    for (int e = 0; e < NE; e++) { g_off[e] = acc; acc += g_cnt[e]; }
}

// ---------------- GEMM 1: H = silu(X@W1a + b1a) * (X@W1b + b1b), gathered rows ----------------
// grid: (FF/64, TOK/128, NE). CTA tile: 128 rows x 64 cols (for BOTH W1a and W1b). BK=32.
__global__ __launch_bounds__(256, 1)
void k_gemm1(const float* __restrict__ b1a, const float* __restrict__ b1b) {
    __shared__ __align__(16) unsigned char sm[29696];
    __half* As = (__half*)sm;                  // 128 x 40
    __half* Ba = (__half*)(sm + 10240);        // 32 x 72
    __half* Bb = (__half*)(sm + 14848);        // 32 x 72
    float*  stage = (float*)(sm + 19456);      // 8 warps x (16 x 20)

    int e   = blockIdx.z;
    int cnt = g_cnt[e];
    int m0  = blockIdx.y * 128;
    if (m0 >= cnt) return;
    int n0  = blockIdx.x * 64;

    int tid = threadIdx.x, warp = tid >> 5, lane = tid & 31;
    int wm = warp >> 1, wn = warp & 1;

    // A load mapping: rows r0 and 64+r0, 4 chunks of 8 halves per row
    int r0 = tid >> 2;
    int ca = (tid & 3) * 8;
    int tok0 = (m0 + r0      < cnt) ? g_tlist[e * TOK + m0 + r0]      : -1;
    int tok1 = (m0 + 64 + r0 < cnt) ? g_tlist[e * TOK + m0 + 64 + r0] : -1;

    // B load mapping: 32 rows x 64 cols, one uint4 per thread per matrix
    int br = tid >> 3;
    int cb = (tid & 7) * 8;
    const __half* W1aB = g_W1ah + (size_t)e * DD * FF;
    const __half* W1bB = g_W1bh + (size_t)e * DD * FF;

    wmma::fragment<wmma::accumulator, 16, 16, 16, float> accA[2][2], accB[2][2];
#pragma unroll
    for (int i = 0; i < 2; i++)
#pragma unroll
        for (int j = 0; j < 2; j++) {
            wmma::fill_fragment(accA[i][j], 0.0f);
            wmma::fill_fragment(accB[i][j], 0.0f);
        }

    const uint4 zz = make_uint4(0, 0, 0, 0);
    for (int k = 0; k < DD; k += 32) {
        uint4 va = (tok0 >= 0) ? *(const uint4*)(g_Xh + (size_t)tok0 * DD + k + ca) : zz;
        uint4 vb = (tok1 >= 0) ? *(const uint4*)(g_Xh + (size_t)tok1 * DD + k + ca) : zz;
        *(uint4*)(As + (size_t)r0 * 40 + ca)        = va;
        *(uint4*)(As + (size_t)(64 + r0) * 40 + ca) = vb;
        *(uint4*)(Ba + (size_t)br * 72 + cb) = *(const uint4*)(W1aB + (size_t)(k + br) * FF + n0 + cb);
        *(uint4*)(Bb + (size_t)br * 72 + cb) = *(const uint4*)(W1bB + (size_t)(k + br) * FF + n0 + cb);
        __syncthreads();

#pragma unroll
        for (int kk = 0; kk < 32; kk += 16) {
            wmma::fragment<wmma::matrix_a, 16, 16, 16, __half, wmma::row_major> af[2];
            wmma::fragment<wmma::matrix_b, 16, 16, 16, __half, wmma::row_major> bfa[2], bfb[2];
#pragma unroll
            for (int i = 0; i < 2; i++)
                wmma::load_matrix_sync(af[i], As + (size_t)(wm * 32 + i * 16) * 40 + kk, 40);
#pragma unroll
            for (int j = 0; j < 2; j++) {
                wmma::load_matrix_sync(bfa[j], Ba + (size_t)kk * 72 + wn * 32 + j * 16, 72);
                wmma::load_matrix_sync(bfb[j], Bb + (size_t)kk * 72 + wn * 32 + j * 16, 72);
            }
#pragma unroll
            for (int i = 0; i < 2; i++)
#pragma unroll
                for (int j = 0; j < 2; j++) {
                    wmma::mma_sync(accA[i][j], af[i], bfa[j], accA[i][j]);
                    wmma::mma_sync(accB[i][j], af[i], bfb[j], accB[i][j]);
                }
        }
        __syncthreads();
    }

    // Epilogue: stage 16x16 tiles through smem, fuse bias + silu(a)*b, write fp16 H
    float* stg = stage + warp * 320;          // 16 x 20
    int off_e = g_off[e];
    int erow = lane >> 1;
    int ecb  = (lane & 1) * 8;

#pragma unroll
    for (int i = 0; i < 2; i++) {
        int m = m0 + wm * 32 + i * 16 + erow;
#pragma unroll
        for (int j = 0; j < 2; j++) {
            int nc = n0 + wn * 32 + j * 16 + ecb;

            wmma::store_matrix_sync(stg, accA[i][j], 20, wmma::mem_row_major);
            __syncwarp();
            float sa[8];
#pragma unroll
            for (int q = 0; q < 8; q++) {
                float a = stg[erow * 20 + ecb + q] + __ldg(&b1a[(size_t)e * FF + nc + q]);
                sa[q] = a / (1.0f + __expf(-a));
            }
            __syncwarp();
            wmma::store_matrix_sync(stg, accB[i][j], 20, wmma::mem_row_major);
            __syncwarp();
            if (m < cnt) {
                __align__(16) __half hv[8];
#pragma unroll
                for (int q = 0; q < 8; q++) {
                    float b = stg[erow * 20 + ecb + q] + __ldg(&b1b[(size_t)e * FF + nc + q]);
                    hv[q] = __float2half_rn(sa[q] * b);
                }
                *(uint4*)(&g_H[(size_t)(off_e + m) * FF + nc]) = *(uint4*)hv;
            }
            __syncwarp();
        }
    }
}

// ---------------- GEMM 2: Y = H @ W2 + b2 (contiguous rows per expert) ----------------
// grid: (DD/64, TOK/128, NE). K = FF = 4096, BK=32.
__global__ __launch_bounds__(256, 1)
void k_gemm2(const float* __restrict__ b2) {
    __shared__ __align__(16) unsigned char sm[25088];
    __half* As = (__half*)sm;                  // 128 x 40
    __half* Bs = (__half*)(sm + 10240);        // 32 x 72
    float*  stage = (float*)(sm + 14848);      // 8 warps x (16 x 20)

    int e   = blockIdx.z;
    int cnt = g_cnt[e];
    int m0  = blockIdx.y * 128;
    if (m0 >= cnt) return;
    int n0  = blockIdx.x * 64;

    int tid = threadIdx.x, warp = tid >> 5, lane = tid & 31;
    int wm = warp >> 1, wn = warp & 1;

    int off_e = g_off[e];
    int r0 = tid >> 2;
    int ca = (tid & 3) * 8;
    bool v0 = (m0 + r0      < cnt);
    bool v1 = (m0 + 64 + r0 < cnt);
    const __half* Arow0 = g_H + (size_t)(off_e + m0 + r0) * FF;
    const __half* Arow1 = g_H + (size_t)(off_e + m0 + 64 + r0) * FF;

    int br = tid >> 3;
    int cb = (tid & 7) * 8;
    const __half* W2B = g_W2h + (size_t)e * FF * DD;

    wmma::fragment<wmma::accumulator, 16, 16, 16, float> acc[2][2];
#pragma unroll
    for (int i = 0; i < 2; i++)
#pragma unroll
        for (int j = 0; j < 2; j++) wmma::fill_fragment(acc[i][j], 0.0f);

    const uint4 zz = make_uint4(0, 0, 0, 0);
    for (int k = 0; k < FF; k += 32) {
        uint4 va = v0 ? *(const uint4*)(Arow0 + k + ca) : zz;
        uint4 vb = v1 ? *(const uint4*)(Arow1 + k + ca) : zz;
        *(uint4*)(As + (size_t)r0 * 40 + ca)        = va;
        *(uint4*)(As + (size_t)(64 + r0) * 40 + ca) = vb;
        *(uint4*)(Bs + (size_t)br * 72 + cb) = *(const uint4*)(W2B + (size_t)(k + br) * DD + n0 + cb);
        __syncthreads();

#pragma unroll
        for (int kk = 0; kk < 32; kk += 16) {
            wmma::fragment<wmma::matrix_a, 16, 16, 16, __half, wmma::row_major> af[2];
            wmma::fragment<wmma::matrix_b, 16, 16, 16, __half, wmma::row_major> bf[2];
#pragma unroll
            for (int i = 0; i < 2; i++)
                wmma::load_matrix_sync(af[i], As + (size_t)(wm * 32 + i * 16) * 40 + kk, 40);
#pragma unroll
            for (int j = 0; j < 2; j++)
                wmma::load_matrix_sync(bf[j], Bs + (size_t)kk * 72 + wn * 32 + j * 16, 72);
#pragma unroll
            for (int i = 0; i < 2; i++)
#pragma unroll
                for (int j = 0; j < 2; j++)
                    wmma::mma_sync(acc[i][j], af[i], bf[j], acc[i][j]);
        }
        __syncthreads();
    }

    float* stg = stage + warp * 320;
    int erow = lane >> 1;
    int ecb  = (lane & 1) * 8;

#pragma unroll
    for (int i = 0; i < 2; i++) {
        int m = m0 + wm * 32 + i * 16 + erow;
#pragma unroll
        for (int j = 0; j < 2; j++) {
            int nc = n0 + wn * 32 + j * 16 + ecb;
            wmma::store_matrix_sync(stg, acc[i][j], 20, wmma::mem_row_major);
            __syncwarp();
            if (m < cnt) {
                __align__(16) float yv[8];
#pragma unroll
                for (int q = 0; q < 8; q++)
                    yv[q] = stg[erow * 20 + ecb + q] + __ldg(&b2[(size_t)e * DD + nc + q]);
                float* dst = &g_Y[(size_t)(off_e + m) * DD + nc];
                *(float4*)(dst)     = *(float4*)(yv);
                *(float4*)(dst + 4) = *(float4*)(yv + 4);
            }
            __syncwarp();
        }
    }
}

// ---------------- combine: out[t] = w0*Y[slot0] + w1*Y[slot1] ----------------
__global__ void k_combine(float* __restrict__ out) {
    int t = blockIdx.x;
    int e0 = g_exp[2 * t], e1 = g_exp[2 * t + 1];
    size_t r0 = (size_t)(g_off[e0] + g_loc[2 * t]);
    size_t r1 = (size_t)(g_off[e1] + g_loc[2 * t + 1]);
    float w0 = g_gw[2 * t], w1 = g_gw[2 * t + 1];

    const float4* y0 = (const float4*)(g_Y + r0 * DD);
    const float4* y1 = (const float4*)(g_Y + r1 * DD);
    float4 a = y0[threadIdx.x];
    float4 b = y1[threadIdx.x];
    float4 o;
    o.x = w0 * a.x + w1 * b.x;
    o.y = w0 * a.y + w1 * b.y;
    o.z = w0 * a.z + w1 * b.z;
    o.w = w0 * a.w + w1 * b.w;
    ((float4*)(out + (size_t)t * DD))[threadIdx.x] = o;
}

// ---------------- launch ----------------
extern "C" void kernel_launch(void* const* d_in, const int* in_sizes, int n_in,
                              void* d_out, int out_size) {
    const float* x   = (const float*)d_in[0];
    const float* lnw = (const float*)d_in[1];
    const float* Wg  = (const float*)d_in[2];
    const float* bg  = (const float*)d_in[3];
    const float* W1a = (const float*)d_in[4];
    const float* b1a = (const float*)d_in[5];
    const float* W1b = (const float*)d_in[6];
    const float* b1b = (const float*)d_in[7];
    const float* W2  = (const float*)d_in[8];
    const float* b2  = (const float*)d_in[9];
    float* out = (float*)d_out;

    k_init_cnt<<<1, 32>>>();

    const int n4 = NE * DD * FF / 4;          // float4 count per weight tensor
    k_cvt<<<n4 / 256, 256>>>(W1a, 0);
    k_cvt<<<n4 / 256, 256>>>(W1b, 1);
    k_cvt<<<n4 / 256, 256>>>(W2, 2);

    k_rms_gate<<<TOK, 256>>>(x, lnw, Wg, bg);
    k_prefix<<<1, 1>>>();

    k_gemm1<<<dim3(FF / 64, TOK / 128, NE), 256>>>(b1a, b1b);
    k_gemm2<<<dim3(DD / 64, TOK / 128, NE), 256>>>(b2);

    k_combine<<<TOK, 256>>>(out);
}

// round 7
// speedup vs baseline: 1.2986x; 1.2986x over previous
#include <cuda_runtime.h>
#include <cuda_fp16.h>
#include <mma.h>
#include <cstdint>

using namespace nvcuda;

#define TOK 8192      // B*S
#define DD  1024      // model dim
#define FF  4096      // ffn dim
#define NE  8         // experts
// top-k = 2

// ---------------- cp.async helpers (sm_80 baseline; compiles at compute_103) ----------------
__device__ __forceinline__ uint32_t smem_u32(const void* p) {
    uint32_t a;
    asm("{ .reg .u64 t; cvta.to.shared.u64 t, %1; cvt.u32.u64 %0, t; }" : "=r"(a) : "l"(p));
    return a;
}
__device__ __forceinline__ void cp16(uint32_t dst, const void* src) {
    asm volatile("cp.async.cg.shared.global [%0], [%1], 16;" :: "r"(dst), "l"(src));
}
__device__ __forceinline__ void cp16p(uint32_t dst, const void* src, bool pred) {
    int sz = pred ? 16 : 0;   // sz=0 -> zero-fill 16B, no global access
    asm volatile("cp.async.cg.shared.global [%0], [%1], 16, %2;" :: "r"(dst), "l"(src), "r"(sz));
}
#define CP_COMMIT() asm volatile("cp.async.commit_group;" ::: "memory")
#define CP_WAIT(n)  asm volatile("cp.async.wait_group %0;" :: "n"(n) : "memory")

// ---------------- device scratch (static globals; no allocation) ----------------
__device__ __half g_Xh  [(size_t)TOK * DD];          // rmsnorm'd x, fp16
__device__ __half g_W1ah[(size_t)NE * DD * FF];      // [E][D][F] fp16
__device__ __half g_W1bh[(size_t)NE * DD * FF];
__device__ __half g_W2h [(size_t)NE * FF * DD];      // [E][F][D] fp16
__device__ __half g_H   [(size_t)2 * TOK * FF];      // silu(a)*b per assignment
__device__ float  g_Y   [(size_t)2 * TOK * DD];      // expert output per assignment
__device__ int    g_cnt [NE];
__device__ int    g_off [NE];
__device__ int    g_tlist[NE * TOK];
__device__ int    g_loc [2 * TOK];
__device__ int    g_exp [2 * TOK];
__device__ float  g_gw  [2 * TOK];

// ---------------- small kernels ----------------
__global__ void k_init_cnt() { if (threadIdx.x < NE) g_cnt[threadIdx.x] = 0; }

// fp32 -> fp16 conversion (no transpose; weights already [K][N] row-major per GEMM)
__global__ void k_cvt(const float* __restrict__ src, int which) {
    __half* dst = (which == 0) ? g_W1ah : (which == 1) ? g_W1bh : g_W2h;
    size_t i = (size_t)blockIdx.x * blockDim.x + threadIdx.x;   // float4 index
    float4 v = ((const float4*)src)[i];
    __half2* d2 = (__half2*)dst;
    d2[2 * i]     = __floats2half2_rn(v.x, v.y);
    d2[2 * i + 1] = __floats2half2_rn(v.z, v.w);
}

// RMSNorm + gating + top-2 softmax + scatter. One block per token, 256 threads.
__global__ void k_rms_gate(const float* __restrict__ x,
                           const float* __restrict__ lnw,
                           const float* __restrict__ Wg,
                           const float* __restrict__ bg) {
    int t = blockIdx.x;
    int tid = threadIdx.x, warp = tid >> 5, lane = tid & 31;

    __shared__ float red[8];
    __shared__ float wlog[8][8];
    __shared__ float sscale;

    float4 v = ((const float4*)(x + (size_t)t * DD))[tid];
    float ss = v.x * v.x + v.y * v.y + v.z * v.z + v.w * v.w;
#pragma unroll
    for (int o = 16; o; o >>= 1) ss += __shfl_xor_sync(0xffffffffu, ss, o);
    if (lane == 0) red[warp] = ss;
    __syncthreads();
    if (tid == 0) {
        float tot = 0.f;
#pragma unroll
        for (int w = 0; w < 8; w++) tot += red[w];
        sscale = rsqrtf(tot * (1.0f / (float)DD) + 1.1920928955078125e-7f);
    }
    __syncthreads();
    float s = sscale;

    float4 lw = ((const float4*)lnw)[tid];
    float xn0 = v.x * s * lw.x, xn1 = v.y * s * lw.y;
    float xn2 = v.z * s * lw.z, xn3 = v.w * s * lw.w;

    __half2* xh = (__half2*)(g_Xh + (size_t)t * DD);
    xh[2 * tid]     = __floats2half2_rn(xn0, xn1);
    xh[2 * tid + 1] = __floats2half2_rn(xn2, xn3);

    float p[8];
#pragma unroll
    for (int e = 0; e < 8; e++) p[e] = 0.f;
    int d = tid * 4;
#pragma unroll
    for (int j = 0; j < 4; j++) {
        float xv = (j == 0) ? xn0 : (j == 1) ? xn1 : (j == 2) ? xn2 : xn3;
        const float* wr = Wg + (size_t)(d + j) * NE;
#pragma unroll
        for (int e = 0; e < 8; e++) p[e] += xv * __ldg(&wr[e]);
    }
#pragma unroll
    for (int o = 16; o; o >>= 1) {
#pragma unroll
        for (int e = 0; e < 8; e++) p[e] += __shfl_xor_sync(0xffffffffu, p[e], o);
    }
    if (lane == 0) {
#pragma unroll
        for (int e = 0; e < 8; e++) wlog[warp][e] = p[e];
    }
    __syncthreads();

    if (tid == 0) {
        float lg[8];
#pragma unroll
        for (int e = 0; e < 8; e++) {
            float acc = bg[e];
#pragma unroll
            for (int w = 0; w < 8; w++) acc += wlog[w][e];
            lg[e] = acc;
        }
        int i1 = 0;
#pragma unroll
        for (int e = 1; e < 8; e++) if (lg[e] > lg[i1]) i1 = e;
        int i2 = -1;
#pragma unroll
        for (int e = 0; e < 8; e++) {
            if (e == i1) continue;
            if (i2 < 0 || lg[e] > lg[i2]) i2 = e;
        }
        float z  = expf(lg[i2] - lg[i1]);
        float w1 = 1.0f / (1.0f + z);
        float w2 = 1.0f - w1;

        int p1 = atomicAdd(&g_cnt[i1], 1);
        g_tlist[i1 * TOK + p1] = t;
        g_loc[2 * t] = p1; g_exp[2 * t] = i1; g_gw[2 * t] = w1;

        int p2 = atomicAdd(&g_cnt[i2], 1);
        g_tlist[i2 * TOK + p2] = t;
        g_loc[2 * t + 1] = p2; g_exp[2 * t + 1] = i2; g_gw[2 * t + 1] = w2;
    }
}

__global__ void k_prefix() {
    int acc = 0;
#pragma unroll
    for (int e = 0; e < NE; e++) { g_off[e] = acc; acc += g_cnt[e]; }
}

// ================= GEMM 1: H = silu(X@W1a + b1a) * (X@W1b + b1b) =================
// CTA tile: 128 rows x 64 cols (both matrices). BK=32, 4-stage cp.async pipeline.
// smem stage: A 128x40 half (10240B) | Ba 32x72 (4608B) | Bb 32x72 (4608B) = 19456B; x4 = 77824B
#define G1_STAGE 19456
#define G1_SMEM  (G1_STAGE * 4)
__global__ __launch_bounds__(256, 1)
void k_gemm1(const float* __restrict__ b1a, const float* __restrict__ b1b) {
    extern __shared__ __align__(16) char smem[];
    int e   = blockIdx.z;
    int cnt = g_cnt[e];
    int m0  = blockIdx.y * 128;
    if (m0 >= cnt) return;
    int n0  = blockIdx.x * 64;

    uint32_t sb = smem_u32(smem);
    int tid = threadIdx.x, warp = tid >> 5, lane = tid & 31;
    int wm = warp >> 1, wn = warp & 1;

    // A loader: thread -> row tid>>1, chunk base (tid&1)*2 (2 x 16B per thread)
    int arow = tid >> 1;
    int ac0  = (tid & 1) * 2;
    int tok  = (m0 + arow < cnt) ? g_tlist[e * TOK + m0 + arow] : -1;
    bool apred = (tok >= 0);
    const __half* asrc = g_Xh + (size_t)(apred ? tok : 0) * DD;
    uint32_t aoff0 = (uint32_t)(arow * 80 + ac0 * 16);
    // B loader: row tid>>3, chunk tid&7 (one 16B per matrix)
    int brow = tid >> 3;
    int bc   = tid & 7;
    uint32_t boff = (uint32_t)(brow * 144 + bc * 16);
    const __half* Wa = g_W1ah + (size_t)e * DD * FF + (size_t)brow * FF + n0 + bc * 8;
    const __half* Wb = g_W1bh + (size_t)e * DD * FF + (size_t)brow * FF + n0 + bc * 8;

    wmma::fragment<wmma::accumulator, 16, 16, 16, float> accA[2][2], accB[2][2];
#pragma unroll
    for (int i = 0; i < 2; i++)
#pragma unroll
        for (int j = 0; j < 2; j++) {
            wmma::fill_fragment(accA[i][j], 0.0f);
            wmma::fill_fragment(accB[i][j], 0.0f);
        }

    const int KT = DD / 32;   // 32 k-steps
    auto load_stage = [&](int s, int k0) {
        uint32_t base = sb + s * G1_STAGE;
        cp16p(base + aoff0,      asrc + k0 + ac0 * 8,       apred);
        cp16p(base + aoff0 + 16, asrc + k0 + (ac0 + 1) * 8, apred);
        cp16(base + 10240 + boff, Wa + (size_t)k0 * FF);
        cp16(base + 14848 + boff, Wb + (size_t)k0 * FF);
    };
#pragma unroll
    for (int s = 0; s < 3; s++) { load_stage(s, s * 32); CP_COMMIT(); }

    for (int it = 0; it < KT; ++it) {
        CP_WAIT(2);
        __syncthreads();
        int nk = it + 3;
        if (nk < KT) load_stage(nk & 3, nk * 32);
        CP_COMMIT();

        const __half* A  = (const __half*)(smem + (it & 3) * G1_STAGE);
        const __half* Ba = A + 5120;   // 10240B
        const __half* Bb = A + 7424;   // 14848B
#pragma unroll
        for (int kk = 0; kk < 32; kk += 16) {
            wmma::fragment<wmma::matrix_a, 16, 16, 16, __half, wmma::row_major> af[2];
            wmma::fragment<wmma::matrix_b, 16, 16, 16, __half, wmma::row_major> bfa[2], bfb[2];
#pragma unroll
            for (int i = 0; i < 2; i++)
                wmma::load_matrix_sync(af[i], A + (size_t)(wm * 32 + i * 16) * 40 + kk, 40);
#pragma unroll
            for (int j = 0; j < 2; j++) {
                wmma::load_matrix_sync(bfa[j], Ba + (size_t)kk * 72 + wn * 32 + j * 16, 72);
                wmma::load_matrix_sync(bfb[j], Bb + (size_t)kk * 72 + wn * 32 + j * 16, 72);
            }
#pragma unroll
            for (int i = 0; i < 2; i++)
#pragma unroll
                for (int j = 0; j < 2; j++) {
                    wmma::mma_sync(accA[i][j], af[i], bfa[j], accA[i][j]);
                    wmma::mma_sync(accB[i][j], af[i], bfb[j], accB[i][j]);
                }
        }
        __syncthreads();
    }

    // Epilogue: stage tiles through smem (reuse stage 0), fuse bias + silu(a)*b
    float* stg = (float*)smem + warp * 320;   // 16 x 20 per warp
    int off_e = g_off[e];
    int erow = lane >> 1;
    int ecb  = (lane & 1) * 8;

#pragma unroll
    for (int i = 0; i < 2; i++) {
        int m = m0 + wm * 32 + i * 16 + erow;
#pragma unroll
        for (int j = 0; j < 2; j++) {
            int nc = n0 + wn * 32 + j * 16 + ecb;
            wmma::store_matrix_sync(stg, accA[i][j], 20, wmma::mem_row_major);
            __syncwarp();
            float sa[8];
#pragma unroll
            for (int q = 0; q < 8; q++) {
                float a = stg[erow * 20 + ecb + q] + __ldg(&b1a[(size_t)e * FF + nc + q]);
                sa[q] = a / (1.0f + __expf(-a));
            }
            __syncwarp();
            wmma::store_matrix_sync(stg, accB[i][j], 20, wmma::mem_row_major);
            __syncwarp();
            if (m < cnt) {
                __align__(16) __half hv[8];
#pragma unroll
                for (int q = 0; q < 8; q++) {
                    float b = stg[erow * 20 + ecb + q] + __ldg(&b1b[(size_t)e * FF + nc + q]);
                    hv[q] = __float2half_rn(sa[q] * b);
                }
                *(uint4*)(&g_H[(size_t)(off_e + m) * FF + nc]) = *(uint4*)hv;
            }
            __syncwarp();
        }
    }
}

// ================= GEMM 2: Y = H @ W2 + b2 =================
// CTA tile: 128 x 128. BK=32, 4-stage cp.async. Warp tile 32x64 (4x2 warp grid).
// smem stage: A 128x40 (10240B) | B 32x136 (8704B) = 18944B; x4 = 75776B
#define G2_STAGE 18944
#define G2_SMEM  (G2_STAGE * 4)
__global__ __launch_bounds__(256, 1)
void k_gemm2(const float* __restrict__ b2) {
    extern __shared__ __align__(16) char smem[];
    int e   = blockIdx.z;
    int cnt = g_cnt[e];
    int m0  = blockIdx.y * 128;
    if (m0 >= cnt) return;
    int n0  = blockIdx.x * 128;

    uint32_t sb = smem_u32(smem);
    int tid = threadIdx.x, warp = tid >> 5, lane = tid & 31;
    int wm = warp >> 1, wn = warp & 1;

    int off_e = g_off[e];
    // A loader
    int arow = tid >> 1;
    int ac0  = (tid & 1) * 2;
    bool apred = (m0 + arow < cnt);
    const __half* asrc = g_H + (size_t)(off_e + (apred ? m0 + arow : 0)) * FF;
    uint32_t aoff0 = (uint32_t)(arow * 80 + ac0 * 16);
    // B loader: 2 vectors/thread: idx = tid*2+{0,1}: row idx>>4, chunk idx&15
    int bi = tid * 2;
    int br0 = bi >> 4, bc0 = bi & 15;
    int br1 = (bi + 1) >> 4, bc1 = (bi + 1) & 15;
    uint32_t boff0 = (uint32_t)(br0 * 272 + bc0 * 16);
    uint32_t boff1 = (uint32_t)(br1 * 272 + bc1 * 16);
    const __half* WB = g_W2h + (size_t)e * FF * DD + n0;

    wmma::fragment<wmma::accumulator, 16, 16, 16, float> acc[2][4];
#pragma unroll
    for (int i = 0; i < 2; i++)
#pragma unroll
        for (int j = 0; j < 4; j++) wmma::fill_fragment(acc[i][j], 0.0f);

    const int KT = FF / 32;   // 128 k-steps
    auto load_stage = [&](int s, int k0) {
        uint32_t base = sb + s * G2_STAGE;
        cp16p(base + aoff0,      asrc + k0 + ac0 * 8,       apred);
        cp16p(base + aoff0 + 16, asrc + k0 + (ac0 + 1) * 8, apred);
        cp16(base + 10240 + boff0, WB + (size_t)(k0 + br0) * DD + bc0 * 8);
        cp16(base + 10240 + boff1, WB + (size_t)(k0 + br1) * DD + bc1 * 8);
    };
#pragma unroll
    for (int s = 0; s < 3; s++) { load_stage(s, s * 32); CP_COMMIT(); }

    for (int it = 0; it < KT; ++it) {
        CP_WAIT(2);
        __syncthreads();
        int nk = it + 3;
        if (nk < KT) load_stage(nk & 3, nk * 32);
        CP_COMMIT();

        const __half* A = (const __half*)(smem + (it & 3) * G2_STAGE);
        const __half* B = A + 5120;   // 10240B
#pragma unroll
        for (int kk = 0; kk < 32; kk += 16) {
            wmma::fragment<wmma::matrix_a, 16, 16, 16, __half, wmma::row_major> af[2];
            wmma::fragment<wmma::matrix_b, 16, 16, 16, __half, wmma::row_major> bf[4];
#pragma unroll
            for (int i = 0; i < 2; i++)
                wmma::load_matrix_sync(af[i], A + (size_t)(wm * 32 + i * 16) * 40 + kk, 40);
#pragma unroll
            for (int j = 0; j < 4; j++)
                wmma::load_matrix_sync(bf[j], B + (size_t)kk * 136 + wn * 64 + j * 16, 136);
#pragma unroll
            for (int i = 0; i < 2; i++)
#pragma unroll
                for (int j = 0; j < 4; j++)
                    wmma::mma_sync(acc[i][j], af[i], bf[j], acc[i][j]);
        }
        __syncthreads();
    }

    float* stg = (float*)smem + warp * 320;
    int erow = lane >> 1;
    int ecb  = (lane & 1) * 8;

#pragma unroll
    for (int i = 0; i < 2; i++) {
        int m = m0 + wm * 32 + i * 16 + erow;
#pragma unroll
        for (int j = 0; j < 4; j++) {
            int nc = n0 + wn * 64 + j * 16 + ecb;
            wmma::store_matrix_sync(stg, acc[i][j], 20, wmma::mem_row_major);
            __syncwarp();
            if (m < cnt) {
                __align__(16) float yv[8];
#pragma unroll
                for (int q = 0; q < 8; q++)
                    yv[q] = stg[erow * 20 + ecb + q] + __ldg(&b2[(size_t)e * DD + nc + q]);
                float* dst = &g_Y[(size_t)(off_e + m) * DD + nc];
                *(float4*)(dst)     = *(float4*)(yv);
                *(float4*)(dst + 4) = *(float4*)(yv + 4);
            }
            __syncwarp();
        }
    }
}

// ---------------- combine: out[t] = w0*Y[slot0] + w1*Y[slot1] ----------------
__global__ void k_combine(float* __restrict__ out) {
    int t = blockIdx.x;
    int e0 = g_exp[2 * t], e1 = g_exp[2 * t + 1];
    size_t r0 = (size_t)(g_off[e0] + g_loc[2 * t]);
    size_t r1 = (size_t)(g_off[e1] + g_loc[2 * t + 1]);
    float w0 = g_gw[2 * t], w1 = g_gw[2 * t + 1];

    const float4* y0 = (const float4*)(g_Y + r0 * DD);
    const float4* y1 = (const float4*)(g_Y + r1 * DD);
    float4 a = y0[threadIdx.x];
    float4 b = y1[threadIdx.x];
    float4 o;
    o.x = w0 * a.x + w1 * b.x;
    o.y = w0 * a.y + w1 * b.y;
    o.z = w0 * a.z + w1 * b.z;
    o.w = w0 * a.w + w1 * b.w;
    ((float4*)(out + (size_t)t * DD))[threadIdx.x] = o;
}

// ---------------- launch ----------------
extern "C" void kernel_launch(void* const* d_in, const int* in_sizes, int n_in,
                              void* d_out, int out_size) {
    const float* x   = (const float*)d_in[0];
    const float* lnw = (const float*)d_in[1];
    const float* Wg  = (const float*)d_in[2];
    const float* bg  = (const float*)d_in[3];
    const float* W1a = (const float*)d_in[4];
    const float* b1a = (const float*)d_in[5];
    const float* W1b = (const float*)d_in[6];
    const float* b1b = (const float*)d_in[7];
    const float* W2  = (const float*)d_in[8];
    const float* b2  = (const float*)d_in[9];
    float* out = (float*)d_out;

    static int attr_done = 0;
    if (!attr_done) {
        cudaFuncSetAttribute(k_gemm1, cudaFuncAttributeMaxDynamicSharedMemorySize, G1_SMEM);
        cudaFuncSetAttribute(k_gemm2, cudaFuncAttributeMaxDynamicSharedMemorySize, G2_SMEM);
        attr_done = 1;
    }

    k_init_cnt<<<1, 32>>>();

    const int n4 = NE * DD * FF / 4;
    k_cvt<<<n4 / 256, 256>>>(W1a, 0);
    k_cvt<<<n4 / 256, 256>>>(W1b, 1);
    k_cvt<<<n4 / 256, 256>>>(W2, 2);

    k_rms_gate<<<TOK, 256>>>(x, lnw, Wg, bg);
    k_prefix<<<1, 1>>>();

    k_gemm1<<<dim3(FF / 64, TOK / 128, NE), 256, G1_SMEM>>>(b1a, b1b);
    k_gemm2<<<dim3(DD / 128, TOK / 128, NE), 256, G2_SMEM>>>(b2);

    k_combine<<<TOK, 256>>>(out);
}

// round 8
// speedup vs baseline: 2.0858x; 1.6062x over previous
#include <cuda_runtime.h>
#include <cuda_fp16.h>
#include <cstdint>

#define TOK 8192      // B*S
#define DD  1024      // model dim
#define FF  4096      // ffn dim
#define NE  8         // experts
// top-k = 2

// ---------------- PTX helpers ----------------
__device__ __forceinline__ uint32_t smem_u32(const void* p) {
    uint32_t a;
    asm("{ .reg .u64 t; cvta.to.shared.u64 t, %1; cvt.u32.u64 %0, t; }" : "=r"(a) : "l"(p));
    return a;
}
__device__ __forceinline__ void cp16(uint32_t dst, const void* src) {
    asm volatile("cp.async.cg.shared.global [%0], [%1], 16;" :: "r"(dst), "l"(src));
}
__device__ __forceinline__ void cp16p(uint32_t dst, const void* src, bool pred) {
    int sz = pred ? 16 : 0;   // sz=0 -> zero-fill 16B
    asm volatile("cp.async.cg.shared.global [%0], [%1], 16, %2;" :: "r"(dst), "l"(src), "r"(sz));
}
#define CP_COMMIT() asm volatile("cp.async.commit_group;" ::: "memory")
#define CP_WAIT(n)  asm volatile("cp.async.wait_group %0;" :: "n"(n) : "memory")

__device__ __forceinline__ void ldsm4(uint32_t& r0, uint32_t& r1, uint32_t& r2, uint32_t& r3, uint32_t a) {
    asm volatile("ldmatrix.sync.aligned.m8n8.x4.shared.b16 {%0,%1,%2,%3}, [%4];"
        : "=r"(r0), "=r"(r1), "=r"(r2), "=r"(r3) : "r"(a));
}
__device__ __forceinline__ void ldsm4t(uint32_t& r0, uint32_t& r1, uint32_t& r2, uint32_t& r3, uint32_t a) {
    asm volatile("ldmatrix.sync.aligned.m8n8.x4.trans.shared.b16 {%0,%1,%2,%3}, [%4];"
        : "=r"(r0), "=r"(r1), "=r"(r2), "=r"(r3) : "r"(a));
}
__device__ __forceinline__ void mma16816(float* d, uint32_t a0, uint32_t a1, uint32_t a2, uint32_t a3,
                                         uint32_t b0, uint32_t b1) {
    asm volatile("mma.sync.aligned.m16n8k16.row.col.f32.f16.f16.f32 "
        "{%0,%1,%2,%3}, {%4,%5,%6,%7}, {%8,%9}, {%0,%1,%2,%3};"
        : "+f"(d[0]), "+f"(d[1]), "+f"(d[2]), "+f"(d[3])
        : "r"(a0), "r"(a1), "r"(a2), "r"(a3), "r"(b0), "r"(b1));
}
#define SWZ(x) ((uint32_t)(x) ^ ((((uint32_t)(x)) >> 3) & 0x70))

// ---------------- device scratch ----------------
__device__ __half g_Xh  [(size_t)TOK * DD];
__device__ __half g_W1ah[(size_t)NE * DD * FF];      // [E][D][F]
__device__ __half g_W1bh[(size_t)NE * DD * FF];
__device__ __half g_W2h [(size_t)NE * FF * DD];      // [E][F][D]
__device__ __half g_H   [(size_t)2 * TOK * FF];
__device__ float  g_Y   [(size_t)2 * TOK * DD];
__device__ int    g_cnt [NE];
__device__ int    g_off [NE];
__device__ int    g_tlist[NE * TOK];
__device__ int    g_loc [2 * TOK];
__device__ int    g_exp [2 * TOK];
__device__ float  g_gw  [2 * TOK];

// ---------------- small kernels ----------------
__global__ void k_init_cnt() { if (threadIdx.x < NE) g_cnt[threadIdx.x] = 0; }

__global__ void k_cvt(const float* __restrict__ src, int which) {
    __half* dst = (which == 0) ? g_W1ah : (which == 1) ? g_W1bh : g_W2h;
    size_t i = (size_t)blockIdx.x * blockDim.x + threadIdx.x;
    float4 v = ((const float4*)src)[i];
    __half2* d2 = (__half2*)dst;
    d2[2 * i]     = __floats2half2_rn(v.x, v.y);
    d2[2 * i + 1] = __floats2half2_rn(v.z, v.w);
}

__global__ void k_rms_gate(const float* __restrict__ x,
                           const float* __restrict__ lnw,
                           const float* __restrict__ Wg,
                           const float* __restrict__ bg) {
    int t = blockIdx.x;
    int tid = threadIdx.x, warp = tid >> 5, lane = tid & 31;

    __shared__ float red[8];
    __shared__ float wlog[8][8];
    __shared__ float sscale;

    float4 v = ((const float4*)(x + (size_t)t * DD))[tid];
    float ss = v.x * v.x + v.y * v.y + v.z * v.z + v.w * v.w;
#pragma unroll
    for (int o = 16; o; o >>= 1) ss += __shfl_xor_sync(0xffffffffu, ss, o);
    if (lane == 0) red[warp] = ss;
    __syncthreads();
    if (tid == 0) {
        float tot = 0.f;
#pragma unroll
        for (int w = 0; w < 8; w++) tot += red[w];
        sscale = rsqrtf(tot * (1.0f / (float)DD) + 1.1920928955078125e-7f);
    }
    __syncthreads();
    float s = sscale;

    float4 lw = ((const float4*)lnw)[tid];
    float xn0 = v.x * s * lw.x, xn1 = v.y * s * lw.y;
    float xn2 = v.z * s * lw.z, xn3 = v.w * s * lw.w;

    __half2* xh = (__half2*)(g_Xh + (size_t)t * DD);
    xh[2 * tid]     = __floats2half2_rn(xn0, xn1);
    xh[2 * tid + 1] = __floats2half2_rn(xn2, xn3);

    float p[8];
#pragma unroll
    for (int e = 0; e < 8; e++) p[e] = 0.f;
    int d = tid * 4;
#pragma unroll
    for (int j = 0; j < 4; j++) {
        float xv = (j == 0) ? xn0 : (j == 1) ? xn1 : (j == 2) ? xn2 : xn3;
        const float* wr = Wg + (size_t)(d + j) * NE;
#pragma unroll
        for (int e = 0; e < 8; e++) p[e] += xv * __ldg(&wr[e]);
    }
#pragma unroll
    for (int o = 16; o; o >>= 1) {
#pragma unroll
        for (int e = 0; e < 8; e++) p[e] += __shfl_xor_sync(0xffffffffu, p[e], o);
    }
    if (lane == 0) {
#pragma unroll
        for (int e = 0; e < 8; e++) wlog[warp][e] = p[e];
    }
    __syncthreads();

    if (tid == 0) {
        float lg[8];
#pragma unroll
        for (int e = 0; e < 8; e++) {
            float acc = bg[e];
#pragma unroll
            for (int w = 0; w < 8; w++) acc += wlog[w][e];
            lg[e] = acc;
        }
        int i1 = 0;
#pragma unroll
        for (int e = 1; e < 8; e++) if (lg[e] > lg[i1]) i1 = e;
        int i2 = -1;
#pragma unroll
        for (int e = 0; e < 8; e++) {
            if (e == i1) continue;
            if (i2 < 0 || lg[e] > lg[i2]) i2 = e;
        }
        float z  = expf(lg[i2] - lg[i1]);
        float w1 = 1.0f / (1.0f + z);
        float w2 = 1.0f - w1;

        int p1 = atomicAdd(&g_cnt[i1], 1);
        g_tlist[i1 * TOK + p1] = t;
        g_loc[2 * t] = p1; g_exp[2 * t] = i1; g_gw[2 * t] = w1;

        int p2 = atomicAdd(&g_cnt[i2], 1);
        g_tlist[i2 * TOK + p2] = t;
        g_loc[2 * t + 1] = p2; g_exp[2 * t + 1] = i2; g_gw[2 * t + 1] = w2;
    }
}

__global__ void k_prefix() {
    int acc = 0;
#pragma unroll
    for (int e = 0; e < NE; e++) { g_off[e] = acc; acc += g_cnt[e]; }
}

// ================= GEMM 1: H = silu(X@W1a+b1a)*(X@W1b+b1b) =================
// CTA 128x64 (both weights), BK=64, 3-stage cp.async, raw mma + swizzled ldmatrix.
// stage: A[128][64] 16KB | Ba[64][64] 8KB | Bb 8KB = 32KB; x3 = 96KB
#define G1_STAGE 32768
#define G1_SMEM  (G1_STAGE * 3)
__global__ __launch_bounds__(256, 2)
void k_gemm1(const float* __restrict__ b1a, const float* __restrict__ b1b) {
    extern __shared__ __align__(16) char smem[];
    int e   = blockIdx.z;
    int cnt = g_cnt[e];
    int m0  = blockIdx.y * 128;
    if (m0 >= cnt) return;
    int n0  = blockIdx.x * 64;

    uint32_t sb = smem_u32(smem);
    int tid = threadIdx.x, warp = tid >> 5, lane = tid & 31;
    int wm = warp >> 1, wn = warp & 1;   // 4x2 warp grid; warp tile 32 x 32 (per matrix)

    // loader mapping: A rows (tid>>3)+32i (i<4), chunk tid&7; B rows (tid>>3)+32i (i<2)
    int lrow = tid >> 3;
    int lc   = tid & 7;
    int tok[4];
    bool ap[4];
#pragma unroll
    for (int i = 0; i < 4; i++) {
        int r = lrow + 32 * i;
        ap[i]  = (m0 + r < cnt);
        tok[i] = ap[i] ? g_tlist[e * TOK + m0 + r] : 0;
    }
    const __half* Wa = g_W1ah + (size_t)e * DD * FF + n0 + lc * 8;
    const __half* Wb = g_W1bh + (size_t)e * DD * FF + n0 + lc * 8;

    float accA[2][4][4], accB[2][4][4];
#pragma unroll
    for (int i = 0; i < 2; i++)
#pragma unroll
        for (int j = 0; j < 4; j++)
#pragma unroll
            for (int q = 0; q < 4; q++) { accA[i][j][q] = 0.f; accB[i][j][q] = 0.f; }

    auto load_stage = [&](int s, int k0) {
        uint32_t base = sb + s * G1_STAGE;
#pragma unroll
        for (int i = 0; i < 4; i++) {
            int r = lrow + 32 * i;
            cp16p(base + SWZ(r * 128 + lc * 16), g_Xh + (size_t)tok[i] * DD + k0 + lc * 8, ap[i]);
        }
#pragma unroll
        for (int i = 0; i < 2; i++) {
            int r = lrow + 32 * i;
            uint32_t o = SWZ(r * 128 + lc * 16);
            cp16(base + 16384 + o, Wa + (size_t)(k0 + r) * FF);
            cp16(base + 24576 + o, Wb + (size_t)(k0 + r) * FF);
        }
    };

    const int ITERS = DD / 64;   // 16
    load_stage(0, 0);  CP_COMMIT();
    load_stage(1, 64); CP_COMMIT();

    // ldmatrix lane addressing (constant parts)
    int l16 = lane & 15, lh = lane >> 4;
    for (int it = 0; it < ITERS; ++it) {
        CP_WAIT(1);
        __syncthreads();
        if (it + 2 < ITERS) load_stage((it + 2) % 3, (it + 2) * 64);
        CP_COMMIT();

        uint32_t Ab  = sb + (it % 3) * G1_STAGE;
        uint32_t Bab = Ab + 16384;
        uint32_t Bbb = Ab + 24576;
#pragma unroll
        for (int kk = 0; kk < 4; kk++) {
            uint32_t a[2][4];
#pragma unroll
            for (int i = 0; i < 2; i++)
                ldsm4(a[i][0], a[i][1], a[i][2], a[i][3],
                      Ab + SWZ((wm * 32 + i * 16 + l16) * 128 + kk * 32 + lh * 16));
#pragma unroll
            for (int jb = 0; jb < 2; jb++) {
                uint32_t boff = SWZ((kk * 16 + l16) * 128 + wn * 64 + jb * 32 + lh * 16);
                uint32_t b0, b1, b2, b3;
                ldsm4t(b0, b1, b2, b3, Bab + boff);
#pragma unroll
                for (int i = 0; i < 2; i++) {
                    mma16816(accA[i][jb * 2],     a[i][0], a[i][1], a[i][2], a[i][3], b0, b1);
                    mma16816(accA[i][jb * 2 + 1], a[i][0], a[i][1], a[i][2], a[i][3], b2, b3);
                }
                ldsm4t(b0, b1, b2, b3, Bbb + boff);
#pragma unroll
                for (int i = 0; i < 2; i++) {
                    mma16816(accB[i][jb * 2],     a[i][0], a[i][1], a[i][2], a[i][3], b0, b1);
                    mma16816(accB[i][jb * 2 + 1], a[i][0], a[i][1], a[i][2], a[i][3], b2, b3);
                }
            }
        }
    }

    // epilogue: direct half2 stores, fused bias + silu(a)*b
    int off_e = g_off[e];
    int r_lo = lane >> 2, cp2 = (lane & 3) * 2;
#pragma unroll
    for (int i = 0; i < 2; i++) {
#pragma unroll
        for (int rr = 0; rr < 2; rr++) {
            int m = m0 + wm * 32 + i * 16 + rr * 8 + r_lo;
            if (m >= cnt) continue;
            __half* Hrow = g_H + (size_t)(off_e + m) * FF;
#pragma unroll
            for (int j = 0; j < 4; j++) {
                int nc = n0 + wn * 32 + j * 8 + cp2;
                float a0 = accA[i][j][rr * 2]     + __ldg(&b1a[(size_t)e * FF + nc]);
                float a1 = accA[i][j][rr * 2 + 1] + __ldg(&b1a[(size_t)e * FF + nc + 1]);
                float v0 = accB[i][j][rr * 2]     + __ldg(&b1b[(size_t)e * FF + nc]);
                float v1 = accB[i][j][rr * 2 + 1] + __ldg(&b1b[(size_t)e * FF + nc + 1]);
                float h0 = a0 / (1.0f + __expf(-a0)) * v0;
                float h1 = a1 / (1.0f + __expf(-a1)) * v1;
                *(__half2*)(Hrow + nc) = __floats2half2_rn(h0, h1);
            }
        }
    }
}

// ================= GEMM 2: Y = H @ W2 + b2 =================
// CTA 128x128, BK=64, B as two 64-col panels (128B rows). warp tile 32x64.
// stage: A 16KB | B 2x8KB = 32KB; x3 = 96KB
#define G2_STAGE 32768
#define G2_SMEM  (G2_STAGE * 3)
__global__ __launch_bounds__(256, 2)
void k_gemm2(const float* __restrict__ b2) {
    extern __shared__ __align__(16) char smem[];
    int e   = blockIdx.z;
    int cnt = g_cnt[e];
    int m0  = blockIdx.y * 128;
    if (m0 >= cnt) return;
    int n0  = blockIdx.x * 128;

    uint32_t sb = smem_u32(smem);
    int tid = threadIdx.x, warp = tid >> 5, lane = tid & 31;
    int wm = warp >> 1, wn = warp & 1;

    int off_e = g_off[e];
    int lrow = tid >> 3;
    int lc   = tid & 7;
    bool ap[4];
    const __half* Arow[4];
#pragma unroll
    for (int i = 0; i < 4; i++) {
        int r = lrow + 32 * i;
        ap[i]   = (m0 + r < cnt);
        Arow[i] = g_H + (size_t)(off_e + (ap[i] ? m0 + r : 0)) * FF;
    }
    const __half* WB = g_W2h + (size_t)e * FF * DD + n0 + lc * 8;

    float acc[2][8][4];
#pragma unroll
    for (int i = 0; i < 2; i++)
#pragma unroll
        for (int j = 0; j < 8; j++)
#pragma unroll
            for (int q = 0; q < 4; q++) acc[i][j][q] = 0.f;

    auto load_stage = [&](int s, int k0) {
        uint32_t base = sb + s * G2_STAGE;
#pragma unroll
        for (int i = 0; i < 4; i++) {
            int r = lrow + 32 * i;
            cp16p(base + SWZ(r * 128 + lc * 16), Arow[i] + k0 + lc * 8, ap[i]);
        }
#pragma unroll
        for (int p = 0; p < 2; p++)
#pragma unroll
            for (int i = 0; i < 2; i++) {
                int r = lrow + 32 * i;
                cp16(base + 16384 + p * 8192 + SWZ(r * 128 + lc * 16),
                     WB + (size_t)(k0 + r) * DD + p * 64);
            }
    };

    const int ITERS = FF / 64;   // 64
    load_stage(0, 0);  CP_COMMIT();
    load_stage(1, 64); CP_COMMIT();

    int l16 = lane & 15, lh = lane >> 4;
    for (int it = 0; it < ITERS; ++it) {
        CP_WAIT(1);
        __syncthreads();
        if (it + 2 < ITERS) load_stage((it + 2) % 3, (it + 2) * 64);
        CP_COMMIT();

        uint32_t Ab = sb + (it % 3) * G2_STAGE;
        uint32_t Bb = Ab + 16384 + wn * 8192;   // this warp's 64-col panel
#pragma unroll
        for (int kk = 0; kk < 4; kk++) {
            uint32_t a[2][4];
#pragma unroll
            for (int i = 0; i < 2; i++)
                ldsm4(a[i][0], a[i][1], a[i][2], a[i][3],
                      Ab + SWZ((wm * 32 + i * 16 + l16) * 128 + kk * 32 + lh * 16));
#pragma unroll
            for (int jb = 0; jb < 4; jb++) {
                uint32_t b0, b1, b2, b3;
                ldsm4t(b0, b1, b2, b3, Bb + SWZ((kk * 16 + l16) * 128 + jb * 32 + lh * 16));
#pragma unroll
                for (int i = 0; i < 2; i++) {
                    mma16816(acc[i][jb * 2],     a[i][0], a[i][1], a[i][2], a[i][3], b0, b1);
                    mma16816(acc[i][jb * 2 + 1], a[i][0], a[i][1], a[i][2], a[i][3], b2, b3);
                }
            }
        }
    }

    int r_lo = lane >> 2, cp2 = (lane & 3) * 2;
#pragma unroll
    for (int i = 0; i < 2; i++) {
#pragma unroll
        for (int rr = 0; rr < 2; rr++) {
            int m = m0 + wm * 32 + i * 16 + rr * 8 + r_lo;
            if (m >= cnt) continue;
            float* Yrow = g_Y + (size_t)(off_e + m) * DD;
#pragma unroll
            for (int j = 0; j < 8; j++) {
                int nc = n0 + wn * 64 + j * 8 + cp2;
                float y0 = acc[i][j][rr * 2]     + __ldg(&b2[(size_t)e * DD + nc]);
                float y1 = acc[i][j][rr * 2 + 1] + __ldg(&b2[(size_t)e * DD + nc + 1]);
                *(float2*)(Yrow + nc) = make_float2(y0, y1);
            }
        }
    }
}

// ---------------- combine ----------------
__global__ void k_combine(float* __restrict__ out) {
    int t = blockIdx.x;
    int e0 = g_exp[2 * t], e1 = g_exp[2 * t + 1];
    size_t r0 = (size_t)(g_off[e0] + g_loc[2 * t]);
    size_t r1 = (size_t)(g_off[e1] + g_loc[2 * t + 1]);
    float w0 = g_gw[2 * t], w1 = g_gw[2 * t + 1];

    const float4* y0 = (const float4*)(g_Y + r0 * DD);
    const float4* y1 = (const float4*)(g_Y + r1 * DD);
    float4 a = y0[threadIdx.x];
    float4 b = y1[threadIdx.x];
    float4 o;
    o.x = w0 * a.x + w1 * b.x;
    o.y = w0 * a.y + w1 * b.y;
    o.z = w0 * a.z + w1 * b.z;
    o.w = w0 * a.w + w1 * b.w;
    ((float4*)(out + (size_t)t * DD))[threadIdx.x] = o;
}

// ---------------- launch ----------------
extern "C" void kernel_launch(void* const* d_in, const int* in_sizes, int n_in,
                              void* d_out, int out_size) {
    const float* x   = (const float*)d_in[0];
    const float* lnw = (const float*)d_in[1];
    const float* Wg  = (const float*)d_in[2];
    const float* bg  = (const float*)d_in[3];
    const float* W1a = (const float*)d_in[4];
    const float* b1a = (const float*)d_in[5];
    const float* W1b = (const float*)d_in[6];
    const float* b1b = (const float*)d_in[7];
    const float* W2  = (const float*)d_in[8];
    const float* b2  = (const float*)d_in[9];
    float* out = (float*)d_out;

    static int attr_done = 0;
    if (!attr_done) {
        cudaFuncSetAttribute(k_gemm1, cudaFuncAttributeMaxDynamicSharedMemorySize, G1_SMEM);
        cudaFuncSetAttribute(k_gemm2, cudaFuncAttributeMaxDynamicSharedMemorySize, G2_SMEM);
        attr_done = 1;
    }

    k_init_cnt<<<1, 32>>>();

    const int n4 = NE * DD * FF / 4;
    k_cvt<<<n4 / 256, 256>>>(W1a, 0);
    k_cvt<<<n4 / 256, 256>>>(W1b, 1);
    k_cvt<<<n4 / 256, 256>>>(W2, 2);

    k_rms_gate<<<TOK, 256>>>(x, lnw, Wg, bg);
    k_prefix<<<1, 1>>>();

    k_gemm1<<<dim3(FF / 64, TOK / 128, NE), 256, G1_SMEM>>>(b1a, b1b);
    k_gemm2<<<dim3(DD / 128, TOK / 128, NE), 256, G2_SMEM>>>(b2);

    k_combine<<<TOK, 256>>>(out);
}